// round 6
// baseline (speedup 1.0000x reference)
#include <cuda_runtime.h>
#include <cstdint>
#include <cstddef>

#define N_NODES 50000
#define FEAT 128

// Scratch (static __device__ globals — no allocation in kernel_launch).
__device__ __align__(16) unsigned char g_needed[N_NODES];
__device__ int                         g_cnt[N_NODES];
__device__ __align__(16) float         g_accT[(size_t)N_NODES * FEAT]; // sum of T[dst] per src
__device__ __align__(16) float         g_T[(size_t)N_NODES * FEAT];    // tanh(X@W1+b1)
__device__ int                         g_is64;                          // edges/node_idx dtype flag

// ---------------------------------------------------------------------------
// Probe index dtype: int64 arrays of values < 2^31 have all-zero odd 32-bit
// words (high halves). int32 (E,2) arrays have dst values at odd words.
// ---------------------------------------------------------------------------
__global__ void probe_kernel(const int* __restrict__ edges_raw, int nwords)
{
    if (threadIdx.x == 0 && blockIdx.x == 0) {
        int any = 0;
        int n = nwords < 2048 ? nwords : 2048;
        for (int i = 1; i < n; i += 2) any |= edges_raw[i];
        g_is64 = (any == 0) ? 1 : 0;
    }
}

// ---------------------------------------------------------------------------
// Mark which src nodes are actually needed (appear in node_idx).
// ---------------------------------------------------------------------------
__global__ void mark_kernel(const void* __restrict__ node_idx, int B)
{
    int i = blockIdx.x * blockDim.x + threadIdx.x;
    if (i < B) {
        long long s = g_is64 ? ((const long long*)node_idx)[i]
                             : (long long)((const int*)node_idx)[i];
        if ((unsigned long long)s < (unsigned long long)N_NODES)
            g_needed[s] = 1;
    }
}

// ---------------------------------------------------------------------------
// GEMM1: T = tanh(X @ W1 + b1), X is [N,128] fp32, W1 [128,128].
// CTA: 512 threads, tile 128 rows x 128 cols, K=128 fully in smem.
// Thread computes 8 rows x 4 cols. A-loads broadcast, B-loads conflict-free.
// ---------------------------------------------------------------------------
__global__ __launch_bounds__(512)
void gemm1_kernel(const float* __restrict__ X,
                  const float* __restrict__ W1,
                  const float* __restrict__ b1,
                  int Nrows)
{
    extern __shared__ float sm[];
    float* sW = sm;            // 128*128
    float* sX = sm + 16384;    // 128*128

    int tid  = threadIdx.x;
    int row0 = blockIdx.x * 128;

    for (int i = tid * 4; i < 16384; i += 512 * 4)
        *(float4*)&sW[i] = *(const float4*)&W1[i];

    for (int i = tid * 4; i < 16384; i += 512 * 4) {
        int r = i >> 7, c = i & 127;
        int gr = row0 + r;
        float4 v = make_float4(0.f, 0.f, 0.f, 0.f);
        if (gr < Nrows) v = *(const float4*)&X[(size_t)gr * FEAT + c];
        *(float4*)&sX[i] = v;
    }
    __syncthreads();

    int tr = tid >> 5;   // 0..15 -> rows tr*8 .. tr*8+7
    int tc = tid & 31;   // 0..31 -> cols tc*4 .. tc*4+3

    float acc[8][4];
    #pragma unroll
    for (int r = 0; r < 8; r++)
        #pragma unroll
        for (int c = 0; c < 4; c++) acc[r][c] = 0.f;

    #pragma unroll 4
    for (int k = 0; k < 128; k += 4) {
        float4 p0 = *(const float4*)&sW[(k + 0) * 128 + tc * 4];
        float4 p1 = *(const float4*)&sW[(k + 1) * 128 + tc * 4];
        float4 p2 = *(const float4*)&sW[(k + 2) * 128 + tc * 4];
        float4 p3 = *(const float4*)&sW[(k + 3) * 128 + tc * 4];
        #pragma unroll
        for (int r = 0; r < 8; r++) {
            float4 a = *(const float4*)&sX[(tr * 8 + r) * 128 + k];
            acc[r][0] += a.x * p0.x + a.y * p1.x + a.z * p2.x + a.w * p3.x;
            acc[r][1] += a.x * p0.y + a.y * p1.y + a.z * p2.y + a.w * p3.y;
            acc[r][2] += a.x * p0.z + a.y * p1.z + a.z * p2.z + a.w * p3.z;
            acc[r][3] += a.x * p0.w + a.y * p1.w + a.z * p2.w + a.w * p3.w;
        }
    }

    float4 bias = *(const float4*)&b1[tc * 4];
    #pragma unroll
    for (int r = 0; r < 8; r++) {
        int gr = row0 + tr * 8 + r;
        if (gr < Nrows) {
            float4 o;
            o.x = tanhf(acc[r][0] + bias.x);
            o.y = tanhf(acc[r][1] + bias.y);
            o.z = tanhf(acc[r][2] + bias.z);
            o.w = tanhf(acc[r][3] + bias.w);
            *(float4*)&g_T[(size_t)gr * FEAT + tc * 4] = o;
        }
    }
}

// ---------------------------------------------------------------------------
// Edge aggregation: for each edge (src,dst) with nonzero value and needed src,
// g_accT[src] += T[dst] (128 floats, one warp: lane does 4 floats via red.v4),
// g_cnt[src] += 1.
// Each warp owns 32 edges: coalesced edge read, ballot, then serialize
// over active lanes with whole-warp cooperative gather+reduce.
// ---------------------------------------------------------------------------
__global__ __launch_bounds__(256)
void edge_kernel(const void* __restrict__ edges,
                 const int* __restrict__ ind_ptr,
                 int E)
{
    int gtid = blockIdx.x * blockDim.x + threadIdx.x;
    int lane = threadIdx.x & 31;
    int warp = gtid >> 5;
    int nw   = (gridDim.x * blockDim.x) >> 5;

    int is64 = g_is64;
    // mask = [1,1,0,0]; self-edges count iff ind < 2 (value 1), else value 0.
    int keep_self = (*ind_ptr < 2);

    for (int base = warp * 32; base < E; base += nw * 32) {
        int e = base + lane;
        int src = 0, dst = 0;
        bool act = false;
        if (e < E) {
            if (is64) {
                longlong2 p = ((const longlong2*)edges)[e];
                src = (int)p.x;
                dst = (int)p.y;
            } else {
                int2 p = ((const int2*)edges)[e];
                src = p.x;
                dst = p.y;
            }
            act = ((src != dst) | keep_self)
                  && ((unsigned)src < (unsigned)N_NODES)
                  && ((unsigned)dst < (unsigned)N_NODES)
                  && g_needed[src];
        }
        unsigned m = __ballot_sync(0xffffffffu, act);
        while (m) {
            int l = __ffs(m) - 1;
            m &= m - 1;
            int s = __shfl_sync(0xffffffffu, src, l);
            int d = __shfl_sync(0xffffffffu, dst, l);
            float4 hv = *(const float4*)&g_T[(size_t)d * FEAT + lane * 4];
            float* dp = &g_accT[(size_t)s * FEAT + lane * 4];
            asm volatile("red.global.add.v4.f32 [%0], {%1,%2,%3,%4};"
                         :: "l"(dp), "f"(hv.x), "f"(hv.y), "f"(hv.z), "f"(hv.w)
                         : "memory");
            if (lane == 0) atomicAdd(&g_cnt[s], 1);
        }
    }
}

// ---------------------------------------------------------------------------
// GEMM2 (B rows only): out[i] = flag_i * ((accT[s_i]/cnt_i) @ W2 + b2),
// s_i = node_idx[i]; flag = 0 when cnt==0 (reference gives exact 0 there).
// CTA: 256 threads, tile 64 rows x 128 cols.
// ---------------------------------------------------------------------------
__global__ __launch_bounds__(256)
void gemm2_kernel(const void* __restrict__ node_idx,
                  const float* __restrict__ W2,
                  const float* __restrict__ b2,
                  float* __restrict__ out,
                  int B)
{
    extern __shared__ float sm[];
    float* sW    = sm;                    // 128*128
    float* sA    = sm + 16384;            // 64*128
    float* sFlag = sm + 16384 + 8192;     // 64

    int tid = threadIdx.x;
    int i0  = blockIdx.x * 64;
    int is64 = g_is64;

    for (int i = tid * 4; i < 16384; i += 256 * 4)
        *(float4*)&sW[i] = *(const float4*)&W2[i];

    {
        int r = tid >> 2;         // 0..63 local row
        int q = tid & 3;          // quarter of the 128 cols
        int i = i0 + r;
        float  scale = 0.f;
        size_t s = 0;
        int    c = 0;
        bool   valid = (i < B);
        if (valid) {
            long long sv = is64 ? ((const long long*)node_idx)[i]
                                : (long long)((const int*)node_idx)[i];
            if ((unsigned long long)sv < (unsigned long long)N_NODES) {
                s = (size_t)sv;
                c = g_cnt[s];
            } else {
                valid = false;
            }
            scale = (c > 0) ? (1.f / (float)c) : 0.f;
        }
        if (q == 0) sFlag[r] = (valid && c > 0) ? 1.f : 0.f;
        #pragma unroll
        for (int j = 0; j < 8; j++) {
            int col = q * 32 + j * 4;
            float4 v = make_float4(0.f, 0.f, 0.f, 0.f);
            if (valid) {
                v = *(const float4*)&g_accT[s * FEAT + col];
                v.x *= scale; v.y *= scale; v.z *= scale; v.w *= scale;
            }
            *(float4*)&sA[r * 128 + col] = v;
        }
    }
    __syncthreads();

    int tr = tid >> 5;   // 0..7 -> rows tr*8..tr*8+7
    int tc = tid & 31;   // cols tc*4..tc*4+3

    float acc[8][4];
    #pragma unroll
    for (int r = 0; r < 8; r++)
        #pragma unroll
        for (int c = 0; c < 4; c++) acc[r][c] = 0.f;

    #pragma unroll 4
    for (int k = 0; k < 128; k += 4) {
        float4 p0 = *(const float4*)&sW[(k + 0) * 128 + tc * 4];
        float4 p1 = *(const float4*)&sW[(k + 1) * 128 + tc * 4];
        float4 p2 = *(const float4*)&sW[(k + 2) * 128 + tc * 4];
        float4 p3 = *(const float4*)&sW[(k + 3) * 128 + tc * 4];
        #pragma unroll
        for (int r = 0; r < 8; r++) {
            float4 a = *(const float4*)&sA[(tr * 8 + r) * 128 + k];
            acc[r][0] += a.x * p0.x + a.y * p1.x + a.z * p2.x + a.w * p3.x;
            acc[r][1] += a.x * p0.y + a.y * p1.y + a.z * p2.y + a.w * p3.y;
            acc[r][2] += a.x * p0.z + a.y * p1.z + a.z * p2.z + a.w * p3.z;
            acc[r][3] += a.x * p0.w + a.y * p1.w + a.z * p2.w + a.w * p3.w;
        }
    }

    float4 bias = *(const float4*)&b2[tc * 4];
    #pragma unroll
    for (int r = 0; r < 8; r++) {
        int rl = tr * 8 + r;
        int i  = i0 + rl;
        if (i < B) {
            float f = sFlag[rl];
            float4 o;
            o.x = f * (acc[r][0] + bias.x);
            o.y = f * (acc[r][1] + bias.y);
            o.z = f * (acc[r][2] + bias.z);
            o.w = f * (acc[r][3] + bias.w);
            *(float4*)&out[(size_t)i * FEAT + tc * 4] = o;
        }
    }
}

// ---------------------------------------------------------------------------
// Launch. Inputs (metadata order): edges, node_idx, local_features,
// W1, b1, W2, b2, ind. Index dtype (int32 vs int64) detected on-device.
// ---------------------------------------------------------------------------
extern "C" void kernel_launch(void* const* d_in, const int* in_sizes, int n_in,
                              void* d_out, int out_size)
{
    const void*  edges    = d_in[0];
    const void*  node_idx = d_in[1];
    const float* X        = (const float*)d_in[2];
    const float* W1       = (const float*)d_in[3];
    const float* b1       = (const float*)d_in[4];
    const float* W2       = (const float*)d_in[5];
    const float* b2       = (const float*)d_in[6];
    const int*   ind      = (const int*)d_in[7];

    int E = in_sizes[0] / 2;
    int B = in_sizes[1];
    int N = in_sizes[2] / FEAT;
    float* out = (float*)d_out;

    void *p_needed, *p_cnt, *p_acc;
    cudaGetSymbolAddress(&p_needed, g_needed);
    cudaGetSymbolAddress(&p_cnt,    g_cnt);
    cudaGetSymbolAddress(&p_acc,    g_accT);

    cudaMemsetAsync(p_needed, 0, N_NODES);
    cudaMemsetAsync(p_cnt,    0, N_NODES * sizeof(int));
    cudaMemsetAsync(p_acc,    0, (size_t)N_NODES * FEAT * sizeof(float));

    cudaFuncSetAttribute(gemm1_kernel, cudaFuncAttributeMaxDynamicSharedMemorySize, 131072);
    cudaFuncSetAttribute(gemm2_kernel, cudaFuncAttributeMaxDynamicSharedMemorySize, 98560);

    probe_kernel<<<1, 32>>>((const int*)edges, in_sizes[0]);
    mark_kernel<<<(B + 255) / 256, 256>>>(node_idx, B);
    gemm1_kernel<<<(N + 127) / 128, 512, 131072>>>(X, W1, b1, N);

    int nwarps = (E + 31) / 32;
    edge_kernel<<<(nwarps + 7) / 8, 256>>>(edges, ind, E);

    gemm2_kernel<<<(B + 63) / 64, 256, 98560>>>(node_idx, W2, b2, out, B);
}